// round 13
// baseline (speedup 1.0000x reference)
#include <cuda_runtime.h>
#include <cstddef>

#define CIN 128
#define HW  (112 * 112)
#define WWI 112
#define OWW 56

typedef unsigned long long ull;
__device__ __forceinline__ ull pack2(float a, float b) {
    ull r; asm("mov.b64 %0, {%1, %2};" : "=l"(r) : "f"(a), "f"(b)); return r;
}
__device__ __forceinline__ void unpack2(ull v, float& a, float& b) {
    asm("mov.b64 {%0, %1}, %2;" : "=f"(a), "=f"(b) : "l"(v));
}
__device__ __forceinline__ void ffma2(ull& acc, ull x, ull w) {
    asm("fma.rn.f32x2 %0, %1, %2, %0;" : "+l"(acc) : "l"(x), "l"(w));
}

// smem: ws[128][9][12] = 13824 f = 55.3 KB.
// After phase A, part[8][512] (4096 f) and red[512] alias the ws region.
#define WS_F  13824
#define PSTR  512
#define SM_F  WS_F

__global__ void __launch_bounds__(256, 4)
pasa_fused_kernel(const float* __restrict__ x,  const float* __restrict__ cw,
                  const float* __restrict__ bnw, const float* __restrict__ bnb,
                  const float* __restrict__ bnm, const float* __restrict__ bnv,
                  float* __restrict__ out)
{
    extern __shared__ float sm[];
    float* ws   = sm;                  // [c*108 + tap*12 + sc]
    float* part = sm;                  // alias after phase A
    float* red  = sm + 8 * PSTR;       // alias (4096..4608 < 13824)

    const int oh  = blockIdx.x;          // 0..55
    const int n   = blockIdx.y;          // 0..7
    const int tid = threadIdx.x;
    const int w   = tid >> 5;            // warp -> channels 16w..16w+15
    const int lane = tid & 31;
    const int l    = lane < 28 ? lane : 27;
    const bool act = lane < 28;

    // stage weights: cw[sc][c][tap] -> ws[c*108 + tap*12 + sc]
    for (int i = tid; i < 10368; i += 256) {
        float v = cw[i];
        int sc = i / 1152, r = i - sc * 1152, c = r / 9, tap = r - c * 9;
        ws[c * 108 + tap * 12 + sc] = v;
    }
    __syncthreads();

    int ihs[3];
#pragma unroll
    for (int d = 0; d < 3; ++d) { int v = 2 * oh - 1 + d; ihs[d] = v < 0 ? -v : v; }
    const float* xn = x + (size_t)n * CIN * HW + (size_t)(w * 16) * HW;
    const int cb = 4 * l;

    // ---------------- Phase A: sigma partials ----------------
    ull a01 = 0, a23 = 0, a45 = 0, a67 = 0;  float a8 = 0.f;
    ull b01 = 0, b23 = 0, b45 = 0, b67 = 0;  float b8 = 0.f;

    for (int cc = 0; cc < 16; ++cc) {
        const float* xc = xn + (size_t)cc * HW;
        float xv[3][5];
#pragma unroll
        for (int d = 0; d < 3; ++d) {
            const float4 v = *(const float4*)(xc + ihs[d] * WWI + cb);
            float left = __shfl_up_sync(0xffffffffu, v.w, 1);
            if (lane == 0) left = v.y;           // reflect col -1 -> col 1
            xv[d][0] = left; xv[d][1] = v.x; xv[d][2] = v.y;
            xv[d][3] = v.z;  xv[d][4] = v.w;
        }
        const float* wc = ws + (w * 16 + cc) * 108;
#pragma unroll
        for (int dy = 0; dy < 3; ++dy)
#pragma unroll
            for (int dx = 0; dx < 3; ++dx) {
                const float* wt = wc + (dy * 3 + dx) * 12;
                const ulonglong2 u0 = *(const ulonglong2*)wt;
                const ulonglong2 u1 = *(const ulonglong2*)(wt + 4);
                const float w8 = wt[8];
                const float xa = xv[dy][dx], xb = xv[dy][dx + 2];
                const ull da = pack2(xa, xa), db = pack2(xb, xb);
                ffma2(a01, da, u0.x); ffma2(a23, da, u0.y);
                ffma2(a45, da, u1.x); ffma2(a67, da, u1.y); a8 += xa * w8;
                ffma2(b01, db, u0.x); ffma2(b23, db, u0.y);
                ffma2(b45, db, u1.x); ffma2(b67, db, u1.y); b8 += xb * w8;
            }
    }
    __syncthreads();   // ws reads done; part/red may alias it

    if (act) {
        float s[9];
        unpack2(a01, s[0], s[1]); unpack2(a23, s[2], s[3]);
        unpack2(a45, s[4], s[5]); unpack2(a67, s[6], s[7]); s[8] = a8;
        float* pa = part + w * PSTR + (2 * l) * 9;
#pragma unroll
        for (int sc = 0; sc < 9; ++sc) pa[sc] = s[sc];
        unpack2(b01, s[0], s[1]); unpack2(b23, s[2], s[3]);
        unpack2(b45, s[4], s[5]); unpack2(b67, s[6], s[7]); s[8] = b8;
#pragma unroll
        for (int sc = 0; sc < 9; ++sc) pa[9 + sc] = s[sc];
    }
    __syncthreads();

    // reduce over 8 warps + BN + clamp
    for (int i = tid; i < 504; i += 256) {
        float ssum = 0.f;
#pragma unroll
        for (int g = 0; g < 8; ++g) ssum += part[g * PSTR + i];
        const int sc = i % 9;
        const float scl = __ldg(bnw + sc) * rsqrtf(__ldg(bnv + sc) + 1e-5f);
        red[i] = fmaxf(ssum * scl + (__ldg(bnb + sc) - __ldg(bnm + sc) * scl), 1e-4f);
    }
    __syncthreads();
    // normalize per position
    if (tid < 56) {
        float s = 0.f;
#pragma unroll
        for (int sc = 0; sc < 9; ++sc) s += red[tid * 9 + sc];
        const float inv = 1.f / s;
#pragma unroll
        for (int sc = 0; sc < 9; ++sc) red[tid * 9 + sc] *= inv;
    }
    __syncthreads();

    // ---------------- Phase B: apply ----------------
    ull sp[9];
#pragma unroll
    for (int t = 0; t < 9; ++t)
        sp[t] = pack2(red[(2 * l) * 9 + t], red[(2 * l) * 9 + 9 + t]);

    float* on = out + ((size_t)(n * CIN + w * 16) * OWW + oh) * OWW + 2 * l;

    for (int cc = 0; cc < 16; ++cc) {
        const float* xc = xn + (size_t)cc * HW;
        ull acc = 0;
#pragma unroll
        for (int d = 0; d < 3; ++d) {
            const float4 v = *(const float4*)(xc + ihs[d] * WWI + cb);
            float left = __shfl_up_sync(0xffffffffu, v.w, 1);
            if (lane == 0) left = v.y;
            ffma2(acc, pack2(left, v.y), sp[d * 3 + 0]);
            ffma2(acc, pack2(v.x,  v.z), sp[d * 3 + 1]);
            ffma2(acc, pack2(v.y,  v.w), sp[d * 3 + 2]);
        }
        if (act) {
            float oa, ob; unpack2(acc, oa, ob);
            *(float2*)(on + (size_t)cc * OWW * OWW) = make_float2(oa, ob);
        }
    }
}

extern "C" void kernel_launch(void* const* d_in, const int* in_sizes, int n_in,
                              void* d_out, int out_size)
{
    const float* x   = (const float*)d_in[0];
    const float* cw  = (const float*)d_in[1];
    const float* bnw = (const float*)d_in[2];
    const float* bnb = (const float*)d_in[3];
    const float* bnm = (const float*)d_in[4];
    const float* bnv = (const float*)d_in[5];
    cudaFuncSetAttribute(pasa_fused_kernel,
                         cudaFuncAttributeMaxDynamicSharedMemorySize,
                         SM_F * sizeof(float));
    dim3 grid(OWW, 8);
    pasa_fused_kernel<<<grid, 256, SM_F * sizeof(float)>>>(
        x, cw, bnw, bnb, bnm, bnv, (float*)d_out);
}

// round 15
// speedup vs baseline: 1.4945x; 1.4945x over previous
#include <cuda_runtime.h>
#include <cstddef>

#define CIN 128
#define HW  (112 * 112)
#define WWI 112
#define OWW 56

typedef unsigned long long ull;
__device__ __forceinline__ ull pack2(float a, float b) {
    ull r; asm("mov.b64 %0, {%1, %2};" : "=l"(r) : "f"(a), "f"(b)); return r;
}
__device__ __forceinline__ void unpack2(ull v, float& a, float& b) {
    asm("mov.b64 {%0, %1}, %2;" : "=f"(a), "=f"(b) : "l"(v));
}
__device__ __forceinline__ void ffma2(ull& acc, ull x, ull w) {
    asm("fma.rn.f32x2 %0, %1, %2, %0;" : "+l"(acc) : "l"(x), "l"(w));
}

// smem: ws[128][9][12]=13824f | part[8][512]=4096f | red[512] -> 18432f = 73.7KB
#define WS_F   13824
#define PSTR   512
#define RED_O  (WS_F + 8 * PSTR)
#define SM_F   (RED_O + 512)

// FMA block for one channel; cur regs die after the xv extraction + FMAs.
__device__ __forceinline__ void chan_fma(
    const float4 cur0, const float4 cur1, const float4 cur2,
    int lane, const float* __restrict__ wc,
    ull& a01, ull& a23, ull& a45, ull& a67, float& a8,
    ull& b01, ull& b23, ull& b45, ull& b67, float& b8)
{
    float xv[3][5];
    const float4 cr[3] = {cur0, cur1, cur2};
#pragma unroll
    for (int d = 0; d < 3; ++d) {
        float left = __shfl_up_sync(0xffffffffu, cr[d].w, 1);
        if (lane == 0) left = cr[d].y;       // reflect col -1 -> col 1
        xv[d][0] = left;    xv[d][1] = cr[d].x; xv[d][2] = cr[d].y;
        xv[d][3] = cr[d].z; xv[d][4] = cr[d].w;
    }
#pragma unroll
    for (int dy = 0; dy < 3; ++dy)
#pragma unroll
        for (int dx = 0; dx < 3; ++dx) {
            const float* wt = wc + (dy * 3 + dx) * 12;
            const ulonglong2 u0 = *(const ulonglong2*)wt;
            const ulonglong2 u1 = *(const ulonglong2*)(wt + 4);
            const float w8 = wt[8];
            const float xa = xv[dy][dx], xb = xv[dy][dx + 2];
            const ull da = pack2(xa, xa), db = pack2(xb, xb);
            ffma2(a01, da, u0.x); ffma2(a23, da, u0.y);
            ffma2(a45, da, u1.x); ffma2(a67, da, u1.y); a8 += xa * w8;
            ffma2(b01, db, u0.x); ffma2(b23, db, u0.y);
            ffma2(b45, db, u1.x); ffma2(b67, db, u1.y); b8 += xb * w8;
        }
}

__global__ void __launch_bounds__(256, 3)
pasa_fused_kernel(const float* __restrict__ x,  const float* __restrict__ cw,
                  const float* __restrict__ bnw, const float* __restrict__ bnb,
                  const float* __restrict__ bnm, const float* __restrict__ bnv,
                  float* __restrict__ out)
{
    extern __shared__ float sm[];
    float* ws   = sm;                 // [c*108 + tap*12 + sc]
    float* part = sm + WS_F;
    float* red  = sm + RED_O;

    const int oh  = blockIdx.x;          // 0..55
    const int n   = blockIdx.y;          // 0..7
    const int tid = threadIdx.x;
    const int w   = tid >> 5;            // warp -> channels 16w..16w+15
    const int lane = tid & 31;
    const int l    = lane < 28 ? lane : 27;
    const bool act = lane < 28;

    for (int i = tid; i < 10368; i += 256) {
        float v = cw[i];
        int sc = i / 1152, r = i - sc * 1152, c = r / 9, tap = r - c * 9;
        ws[c * 108 + tap * 12 + sc] = v;
    }
    __syncthreads();

    int ihs[3];
#pragma unroll
    for (int d = 0; d < 3; ++d) { int v = 2 * oh - 1 + d; ihs[d] = v < 0 ? -v : v; }
    const float* xn = x + (size_t)n * CIN * HW + (size_t)(w * 16) * HW;
    const int cb = 4 * l;

    // ---------------- Phase A: sigma partials (2-channel interleave) --------
    ull a01 = 0, a23 = 0, a45 = 0, a67 = 0;  float a8 = 0.f;
    ull b01 = 0, b23 = 0, b45 = 0, b67 = 0;  float b8 = 0.f;

    for (int cp = 0; cp < 8; ++cp) {
        const float* x0 = xn + (size_t)(2 * cp) * HW;
        const float* x1 = x0 + HW;
        // issue all 6 loads up front (MLP = 6)
        float4 c00 = *(const float4*)(x0 + ihs[0] * WWI + cb);
        float4 c01 = *(const float4*)(x0 + ihs[1] * WWI + cb);
        float4 c02 = *(const float4*)(x0 + ihs[2] * WWI + cb);
        float4 c10 = *(const float4*)(x1 + ihs[0] * WWI + cb);
        float4 c11 = *(const float4*)(x1 + ihs[1] * WWI + cb);
        float4 c12 = *(const float4*)(x1 + ihs[2] * WWI + cb);
        const float* wc0 = ws + (w * 16 + 2 * cp) * 108;
        chan_fma(c00, c01, c02, lane, wc0,
                 a01, a23, a45, a67, a8, b01, b23, b45, b67, b8);
        chan_fma(c10, c11, c12, lane, wc0 + 108,
                 a01, a23, a45, a67, a8, b01, b23, b45, b67, b8);
    }

    if (act) {
        float s[9];
        unpack2(a01, s[0], s[1]); unpack2(a23, s[2], s[3]);
        unpack2(a45, s[4], s[5]); unpack2(a67, s[6], s[7]); s[8] = a8;
        float* pa = part + w * PSTR + (2 * l) * 9;
#pragma unroll
        for (int sc = 0; sc < 9; ++sc) pa[sc] = s[sc];
        unpack2(b01, s[0], s[1]); unpack2(b23, s[2], s[3]);
        unpack2(b45, s[4], s[5]); unpack2(b67, s[6], s[7]); s[8] = b8;
#pragma unroll
        for (int sc = 0; sc < 9; ++sc) pa[9 + sc] = s[sc];
    }
    __syncthreads();

    for (int i = tid; i < 504; i += 256) {
        float ssum = 0.f;
#pragma unroll
        for (int g = 0; g < 8; ++g) ssum += part[g * PSTR + i];
        const int sc = i % 9;
        const float scl = __ldg(bnw + sc) * rsqrtf(__ldg(bnv + sc) + 1e-5f);
        red[i] = fmaxf(ssum * scl + (__ldg(bnb + sc) - __ldg(bnm + sc) * scl), 1e-4f);
    }
    __syncthreads();
    if (tid < 56) {
        float s = 0.f;
#pragma unroll
        for (int sc = 0; sc < 9; ++sc) s += red[tid * 9 + sc];
        const float inv = 1.f / s;
#pragma unroll
        for (int sc = 0; sc < 9; ++sc) red[tid * 9 + sc] *= inv;
    }
    __syncthreads();

    // ---------------- Phase B: apply (2-channel interleave) ----------------
    ull sp[9];
#pragma unroll
    for (int t = 0; t < 9; ++t)
        sp[t] = pack2(red[(2 * l) * 9 + t], red[(2 * l) * 9 + 9 + t]);

    float* on = out + ((size_t)(n * CIN + w * 16) * OWW + oh) * OWW + 2 * l;

    for (int cp = 0; cp < 8; ++cp) {
        const float* x0 = xn + (size_t)(2 * cp) * HW;
        const float* x1 = x0 + HW;
        float4 v0[3], v1[3];
#pragma unroll
        for (int d = 0; d < 3; ++d) {
            v0[d] = *(const float4*)(x0 + ihs[d] * WWI + cb);
            v1[d] = *(const float4*)(x1 + ihs[d] * WWI + cb);
        }
        ull acc0 = 0, acc1 = 0;
#pragma unroll
        for (int d = 0; d < 3; ++d) {
            float l0 = __shfl_up_sync(0xffffffffu, v0[d].w, 1);
            float l1 = __shfl_up_sync(0xffffffffu, v1[d].w, 1);
            if (lane == 0) { l0 = v0[d].y; l1 = v1[d].y; }
            ffma2(acc0, pack2(l0,      v0[d].y), sp[d * 3 + 0]);
            ffma2(acc0, pack2(v0[d].x, v0[d].z), sp[d * 3 + 1]);
            ffma2(acc0, pack2(v0[d].y, v0[d].w), sp[d * 3 + 2]);
            ffma2(acc1, pack2(l1,      v1[d].y), sp[d * 3 + 0]);
            ffma2(acc1, pack2(v1[d].x, v1[d].z), sp[d * 3 + 1]);
            ffma2(acc1, pack2(v1[d].y, v1[d].w), sp[d * 3 + 2]);
        }
        if (act) {
            float oa, ob;
            unpack2(acc0, oa, ob);
            *(float2*)(on + (size_t)(2 * cp) * OWW * OWW) = make_float2(oa, ob);
            unpack2(acc1, oa, ob);
            *(float2*)(on + (size_t)(2 * cp + 1) * OWW * OWW) = make_float2(oa, ob);
        }
    }
}

extern "C" void kernel_launch(void* const* d_in, const int* in_sizes, int n_in,
                              void* d_out, int out_size)
{
    const float* x   = (const float*)d_in[0];
    const float* cw  = (const float*)d_in[1];
    const float* bnw = (const float*)d_in[2];
    const float* bnb = (const float*)d_in[3];
    const float* bnm = (const float*)d_in[4];
    const float* bnv = (const float*)d_in[5];
    cudaFuncSetAttribute(pasa_fused_kernel,
                         cudaFuncAttributeMaxDynamicSharedMemorySize,
                         SM_F * sizeof(float));
    dim3 grid(OWW, 8);
    pasa_fused_kernel<<<grid, 256, SM_F * sizeof(float)>>>(
        x, cw, bnw, bnb, bnm, bnv, (float*)d_out);
}